// round 6
// baseline (speedup 1.0000x reference)
#include <cuda_runtime.h>
#include <math.h>
#include <stdint.h>

// Problem constants
#define TT    2048
#define HH    4096
#define NHEAD 32
#define NKVH  8
#define HD    128
#define QSIZE 4096          // NHEAD*HD
#define KVSIZE 1024         // NKVH*HD
#define QKVW  6144          // QSIZE + 2*KVSIZE

// Scratch (no cudaMalloc allowed)
__device__ float g_qkv[(size_t)TT * QKVW];     // 48 MB
__device__ float g_attn[(size_t)TT * QSIZE];   // 32 MB
__device__ float g_hid[(size_t)TT * HH];       // 32 MB  (tf32-rounded hidden)
__device__ float g_wqkv[(size_t)HH * QKVW];    // 96 MB  (tf32-rounded w_qkv)
__device__ float g_wo[(size_t)QSIZE * HH];     // 64 MB  (tf32-rounded w_o)

// ---------------------------------------------------------------------------
// Common helpers
// ---------------------------------------------------------------------------
__device__ __forceinline__ float f2tf32(float x) {
    uint32_t u;
    asm("cvt.rna.tf32.f32 %0, %1;" : "=r"(u) : "f"(x));
    return __uint_as_float(u);
}

__device__ __forceinline__ uint32_t smem_u32(const void* p) {
    return (uint32_t)__cvta_generic_to_shared(p);
}

__device__ __forceinline__ void ldsm4(uint32_t& r0, uint32_t& r1, uint32_t& r2,
                                      uint32_t& r3, uint32_t addr) {
    asm volatile("ldmatrix.sync.aligned.m8n8.x4.shared.b16 {%0,%1,%2,%3}, [%4];"
                 : "=r"(r0), "=r"(r1), "=r"(r2), "=r"(r3) : "r"(addr));
}

__device__ __forceinline__ void mma_tf32(float c[4], uint32_t a0, uint32_t a1,
                                         uint32_t a2, uint32_t a3,
                                         uint32_t b0, uint32_t b1) {
    asm volatile(
        "mma.sync.aligned.m16n8k8.row.col.f32.tf32.tf32.f32 "
        "{%0,%1,%2,%3}, {%4,%5,%6,%7}, {%8,%9}, {%0,%1,%2,%3};"
        : "+f"(c[0]), "+f"(c[1]), "+f"(c[2]), "+f"(c[3])
        : "r"(a0), "r"(a1), "r"(a2), "r"(a3), "r"(b0), "r"(b1));
}

__device__ __forceinline__ void cpasync16(uint32_t dst, const void* src) {
    asm volatile("cp.async.cg.shared.global [%0], [%1], 16;"
                 :: "r"(dst), "l"(src));
}

// ---------------------------------------------------------------------------
// Elementwise rna-tf32 rounding pass
// ---------------------------------------------------------------------------
__global__ void round_tf32(const float* __restrict__ in, float* __restrict__ out,
                           int n4) {
    int i = blockIdx.x * blockDim.x + threadIdx.x;
    if (i >= n4) return;
    float4 v = ((const float4*)in)[i];
    v.x = f2tf32(v.x); v.y = f2tf32(v.y);
    v.z = f2tf32(v.z); v.w = f2tf32(v.w);
    ((float4*)out)[i] = v;
}

// ---------------------------------------------------------------------------
// TF32 tensor-core GEMM, cp.async 3-stage pipeline, BK=32.
// C[M,N] = A[M,K] @ B[K,N], row-major; A,B pre-rounded to tf32.
// 128x128x32 CTA tile, 8 warps (2x4), warp tile 64x32.
// A smem [m][k] stride 36 (ldmatrix, conflict-free);
// B smem [k][n] stride 136 (vector fill; direct-LDS fragments, conflict-free).
// ---------------------------------------------------------------------------
#define BM 128
#define BN 128
#define BKK 32
#define ASTR 36
#define BSTR 136
#define STAGE_A (BM * ASTR)            // 4608 floats per A stage
#define STAGE_B (BKK * BSTR)           // 4352 floats per B stage
#define TG_SMEM ((STAGE_A + STAGE_B) * 3 * 4)   // 107520 B

__global__ __launch_bounds__(256) void tgemm(const float* __restrict__ A,
                                             const float* __restrict__ B,
                                             float* __restrict__ C,
                                             int M, int N, int K) {
    extern __shared__ float smp[];
    float* As = smp;                     // [3][BM][ASTR]
    float* Bs = smp + 3 * STAGE_A;       // [3][BKK][BSTR]

    const int tid  = threadIdx.x;
    const int lane = tid & 31;
    const int wid  = tid >> 5;
    const int mwarp = (wid >> 2) * 64;
    const int nwarp = (wid & 3) * 32;
    const int bx = blockIdx.x, by = blockIdx.y;

    // cp.async mapping: A -> thread (row=tid/2, koff=(tid&1)*16), 4x16B
    //                   B -> thread (k=tid/8, n=(tid%8)*16),     4x16B
    const int arow = tid >> 1;
    const int akoff = (tid & 1) * 16;
    const float* Ag = A + (size_t)(by * BM + arow) * K + akoff;
    const uint32_t aDst = smem_u32(&As[arow * ASTR + akoff]);

    const int bk = tid >> 3;
    const int bn = (tid & 7) * 16;
    const float* Bg = B + (size_t)bk * N + bx * BN + bn;
    const uint32_t bDst = smem_u32(&Bs[bk * BSTR + bn]);

    const int KT = K / BKK;

#define ISSUE(kt, s)                                                    \
    {                                                                   \
        const float* a_ = Ag + (kt) * BKK;                              \
        uint32_t ad_ = aDst + (s) * (STAGE_A * 4);                      \
        cpasync16(ad_,      a_);                                        \
        cpasync16(ad_ + 16, a_ + 4);                                    \
        cpasync16(ad_ + 32, a_ + 8);                                    \
        cpasync16(ad_ + 48, a_ + 12);                                   \
        const float* b_ = Bg + (size_t)(kt) * BKK * N;                  \
        uint32_t bd_ = bDst + (s) * (STAGE_B * 4);                      \
        cpasync16(bd_,      b_);                                        \
        cpasync16(bd_ + 16, b_ + 4);                                    \
        cpasync16(bd_ + 32, b_ + 8);                                    \
        cpasync16(bd_ + 48, b_ + 12);                                   \
    }

    ISSUE(0, 0);
    asm volatile("cp.async.commit_group;");
    ISSUE(1, 1);
    asm volatile("cp.async.commit_group;");

    float acc[4][4][4];
#pragma unroll
    for (int mi = 0; mi < 4; mi++)
#pragma unroll
        for (int ni = 0; ni < 4; ni++)
#pragma unroll
            for (int r = 0; r < 4; r++) acc[mi][ni][r] = 0.f;

    const uint32_t aFrag0 =
        smem_u32(As) + ((mwarp + (lane & 15)) * ASTR + (lane >> 4) * 4) * 4;
    const float* bFrag0 = Bs + (lane & 3) * BSTR + nwarp + (lane >> 2);

    for (int kt = 0; kt < KT; kt++) {
        asm volatile("cp.async.wait_group 1;");
        __syncthreads();
        if (kt + 2 < KT) ISSUE(kt + 2, (kt + 2) % 3);
        asm volatile("cp.async.commit_group;");

        const int s = kt % 3;
        const uint32_t aS = aFrag0 + s * (STAGE_A * 4);
        const float* bS = bFrag0 + s * STAGE_B;

#pragma unroll
        for (int ks = 0; ks < 4; ks++) {
            uint32_t aF[4][4];
#pragma unroll
            for (int mi = 0; mi < 4; mi++)
                ldsm4(aF[mi][0], aF[mi][1], aF[mi][2], aF[mi][3],
                      aS + mi * 16 * ASTR * 4 + ks * 32);
            const float* bRow = bS + ks * 8 * BSTR;
#pragma unroll
            for (int ni = 0; ni < 4; ni++) {
                uint32_t b0 = __float_as_uint(bRow[ni * 8]);
                uint32_t b1 = __float_as_uint(bRow[4 * BSTR + ni * 8]);
#pragma unroll
                for (int mi = 0; mi < 4; mi++)
                    mma_tf32(acc[mi][ni], aF[mi][0], aF[mi][1], aF[mi][2],
                             aF[mi][3], b0, b1);
            }
        }
    }

#pragma unroll
    for (int mi = 0; mi < 4; mi++) {
#pragma unroll
        for (int ni = 0; ni < 4; ni++) {
            int r = by * BM + mwarp + mi * 16 + (lane >> 2);
            int c = bx * BN + nwarp + ni * 8 + (lane & 3) * 2;
            *(float2*)&C[(size_t)r * N + c] =
                make_float2(acc[mi][ni][0], acc[mi][ni][1]);
            *(float2*)&C[(size_t)(r + 8) * N + c] =
                make_float2(acc[mi][ni][2], acc[mi][ni][3]);
        }
    }
#undef ISSUE
}

// ---------------------------------------------------------------------------
// RoPE in-place, fp32 math
// ---------------------------------------------------------------------------
__global__ void rope_kernel(const int* __restrict__ pos, float* __restrict__ qkv) {
    const int total = TT * (NHEAD + NKVH) * 64;
    int idx = blockIdx.x * blockDim.x + threadIdx.x;
    if (idx >= total) return;
    int i = idx & 63;
    int h = (idx >> 6) % (NHEAD + NKVH);
    int t = idx / ((NHEAD + NKVH) * 64);
    int col = (h < NHEAD) ? h * HD : QSIZE + (h - NHEAD) * HD;
    float* p = qkv + (size_t)t * QKVW + col + i;
    float inv = exp2f(-(float)i * 0.2958057710522857f);
    float fr = (float)pos[t] * inv;
    float s, c;
    sincosf(fr, &s, &c);
    float x1 = p[0], x2 = p[64];
    p[0]  = x1 * c - x2 * s;
    p[64] = x2 * c + x1 * s;
}

// ---------------------------------------------------------------------------
// Tensor-core flash attention (tf32), causal, GQA group=4. (unchanged R4)
// ---------------------------------------------------------------------------
#define ABQ  128
#define ABKV 64
#define QSTR 132
#define KSTR 132
#define VSTR 136
#define PSTR 68
#define ATT_SMEM ((ABQ * QSTR + ABKV * KSTR + ABKV * VSTR + ABQ * PSTR) * 4)

__global__ __launch_bounds__(256) void attn_tc(const float* __restrict__ qkv,
                                               float* __restrict__ out) {
    extern __shared__ float sm[];
    float* Qs = sm;                       // [128][QSTR]
    float* Ks = Qs + ABQ * QSTR;          // [64][KSTR]
    float* Vs = Ks + ABKV * KSTR;         // [64][VSTR]
    float* Ps = Vs + ABKV * VSTR;         // [128][PSTR]

    const int h  = blockIdx.x;
    const int qb = gridDim.y - 1 - blockIdx.y;   // heavy tiles first
    const int kvh = h >> 2;
    const int tid = threadIdx.x;
    const int lane = tid & 31;
    const int wid = tid >> 5;
    const int q0 = wid * 16;
    const float qsc = 0.08838834764831845f * 1.4426950408889634f;

    {
        const float* qp = qkv + (size_t)(qb * ABQ) * QKVW + h * HD;
        for (int i = tid; i < ABQ * 32; i += 256) {
            int r = i >> 5, c = (i & 31) * 4;
            float4 v = *(const float4*)(qp + (size_t)r * QKVW + c);
            v.x = f2tf32(v.x * qsc); v.y = f2tf32(v.y * qsc);
            v.z = f2tf32(v.z * qsc); v.w = f2tf32(v.w * qsc);
            *(float4*)(Qs + r * QSTR + c) = v;
        }
    }

    float m0 = -1e30f, m1 = -1e30f, l0 = 0.f, l1 = 0.f;
    float o[16][4];
#pragma unroll
    for (int ni = 0; ni < 16; ni++)
#pragma unroll
        for (int r = 0; r < 4; r++) o[ni][r] = 0.f;

    const uint32_t qA = smem_u32(&Qs[(q0 + (lane & 15)) * QSTR + (lane >> 4) * 4]);
    const uint32_t kB = smem_u32(&Ks[(lane & 7) * KSTR + (lane >> 3) * 4]);
    const uint32_t pA = smem_u32(&Ps[(q0 + (lane & 15)) * PSTR + (lane >> 4) * 4]);

    const int rowg0 = qb * ABQ + q0;
    const int jmax = qb * 2 + 1;

    for (int j = 0; j <= jmax; j++) {
        __syncthreads();
        {
            const float* kp = qkv + (size_t)(j * ABKV) * QKVW + QSIZE + kvh * HD;
            const float* vp = kp + KVSIZE;
            for (int i = tid; i < ABKV * 32; i += 256) {
                int r = i >> 5, c = (i & 31) * 4;
                float4 kk = *(const float4*)(kp + (size_t)r * QKVW + c);
                kk.x = f2tf32(kk.x); kk.y = f2tf32(kk.y);
                kk.z = f2tf32(kk.z); kk.w = f2tf32(kk.w);
                *(float4*)(Ks + r * KSTR + c) = kk;
                float4 vv = *(const float4*)(vp + (size_t)r * QKVW + c);
                vv.x = f2tf32(vv.x); vv.y = f2tf32(vv.y);
                vv.z = f2tf32(vv.z); vv.w = f2tf32(vv.w);
                *(float4*)(Vs + r * VSTR + c) = vv;
            }
        }
        __syncthreads();

        if (j * ABKV <= rowg0 + 15) {
            float sA[8][4];
#pragma unroll
            for (int ni = 0; ni < 8; ni++)
#pragma unroll
                for (int r = 0; r < 4; r++) sA[ni][r] = 0.f;

#pragma unroll
            for (int kc = 0; kc < 8; kc++) {
                uint32_t a0[4], a1[4];
                ldsm4(a0[0], a0[1], a0[2], a0[3], qA + kc * 64);
                ldsm4(a1[0], a1[1], a1[2], a1[3], qA + kc * 64 + 32);
#pragma unroll
                for (int ni = 0; ni < 8; ni++) {
                    uint32_t b[4];
                    ldsm4(b[0], b[1], b[2], b[3],
                          kB + ni * 8 * KSTR * 4 + kc * 64);
                    mma_tf32(sA[ni], a0[0], a0[1], a0[2], a0[3], b[0], b[1]);
                    mma_tf32(sA[ni], a1[0], a1[1], a1[2], a1[3], b[2], b[3]);
                }
            }

            if (j * ABKV + ABKV - 1 > rowg0) {
                int rg = rowg0 + (lane >> 2);
#pragma unroll
                for (int ni = 0; ni < 8; ni++) {
                    int c0 = j * ABKV + ni * 8 + (lane & 3) * 2;
                    if (c0     > rg)     sA[ni][0] = -INFINITY;
                    if (c0 + 1 > rg)     sA[ni][1] = -INFINITY;
                    if (c0     > rg + 8) sA[ni][2] = -INFINITY;
                    if (c0 + 1 > rg + 8) sA[ni][3] = -INFINITY;
                }
            }

            float mx0 = -INFINITY, mx1 = -INFINITY;
#pragma unroll
            for (int ni = 0; ni < 8; ni++) {
                mx0 = fmaxf(mx0, fmaxf(sA[ni][0], sA[ni][1]));
                mx1 = fmaxf(mx1, fmaxf(sA[ni][2], sA[ni][3]));
            }
            mx0 = fmaxf(mx0, __shfl_xor_sync(0xffffffffu, mx0, 1));
            mx0 = fmaxf(mx0, __shfl_xor_sync(0xffffffffu, mx0, 2));
            mx1 = fmaxf(mx1, __shfl_xor_sync(0xffffffffu, mx1, 1));
            mx1 = fmaxf(mx1, __shfl_xor_sync(0xffffffffu, mx1, 2));

            float mn0 = fmaxf(m0, mx0), mn1 = fmaxf(m1, mx1);
            float cr0 = exp2f(m0 - mn0), cr1 = exp2f(m1 - mn1);
            m0 = mn0; m1 = mn1;

            float s0 = 0.f, s1 = 0.f;
#pragma unroll
            for (int ni = 0; ni < 8; ni++) {
                float p0 = exp2f(sA[ni][0] - mn0);
                float p1 = exp2f(sA[ni][1] - mn0);
                float p2 = exp2f(sA[ni][2] - mn1);
                float p3 = exp2f(sA[ni][3] - mn1);
                s0 += p0 + p1;
                s1 += p2 + p3;
                sA[ni][0] = f2tf32(p0); sA[ni][1] = f2tf32(p1);
                sA[ni][2] = f2tf32(p2); sA[ni][3] = f2tf32(p3);
            }
            s0 += __shfl_xor_sync(0xffffffffu, s0, 1);
            s0 += __shfl_xor_sync(0xffffffffu, s0, 2);
            s1 += __shfl_xor_sync(0xffffffffu, s1, 1);
            s1 += __shfl_xor_sync(0xffffffffu, s1, 2);
            l0 = l0 * cr0 + s0;
            l1 = l1 * cr1 + s1;
#pragma unroll
            for (int ni = 0; ni < 16; ni++) {
                o[ni][0] *= cr0; o[ni][1] *= cr0;
                o[ni][2] *= cr1; o[ni][3] *= cr1;
            }

            {
                int rq = q0 + (lane >> 2);
                float* pr0 = &Ps[rq * PSTR + (lane & 3) * 2];
                float* pr1 = &Ps[(rq + 8) * PSTR + (lane & 3) * 2];
#pragma unroll
                for (int ni = 0; ni < 8; ni++) {
                    *(float2*)(pr0 + ni * 8) = make_float2(sA[ni][0], sA[ni][1]);
                    *(float2*)(pr1 + ni * 8) = make_float2(sA[ni][2], sA[ni][3]);
                }
            }
            __syncwarp();

#pragma unroll
            for (int sk = 0; sk < 8; sk++) {
                uint32_t a[4];
                ldsm4(a[0], a[1], a[2], a[3], pA + sk * 32);
                const float* vb = &Vs[(sk * 8 + (lane & 3)) * VSTR + (lane >> 2)];
#pragma unroll
                for (int ni = 0; ni < 16; ni++) {
                    uint32_t b0 = __float_as_uint(vb[ni * 8]);
                    uint32_t b1 = __float_as_uint(vb[4 * VSTR + ni * 8]);
                    mma_tf32(o[ni], a[0], a[1], a[2], a[3], b0, b1);
                }
            }
            __syncwarp();
        }
    }

    float i0 = 1.f / l0, i1 = 1.f / l1;
    int rg = qb * ABQ + q0 + (lane >> 2);
    float* op = out + (size_t)rg * QSIZE + h * HD + (lane & 3) * 2;
#pragma unroll
    for (int ni = 0; ni < 16; ni++) {
        *(float2*)(op + ni * 8) =
            make_float2(f2tf32(o[ni][0] * i0), f2tf32(o[ni][1] * i0));
        *(float2*)(op + (size_t)8 * QSIZE + ni * 8) =
            make_float2(f2tf32(o[ni][2] * i1), f2tf32(o[ni][3] * i1));
    }
}

// ---------------------------------------------------------------------------
extern "C" void kernel_launch(void* const* d_in, const int* in_sizes, int n_in,
                              void* d_out, int out_size) {
    const int*   positions = (const int*)d_in[0];
    const float* hidden    = (const float*)d_in[1];
    const float* w_qkv     = (const float*)d_in[2];
    const float* w_o       = (const float*)d_in[3];
    float*       out       = (float*)d_out;

    void *qkv_p, *attn_p, *hid_p, *wqkv_p, *wo_p;
    cudaGetSymbolAddress(&qkv_p, g_qkv);
    cudaGetSymbolAddress(&attn_p, g_attn);
    cudaGetSymbolAddress(&hid_p, g_hid);
    cudaGetSymbolAddress(&wqkv_p, g_wqkv);
    cudaGetSymbolAddress(&wo_p, g_wo);
    float* qkv  = (float*)qkv_p;
    float* attn = (float*)attn_p;
    float* hid  = (float*)hid_p;
    float* wqkv = (float*)wqkv_p;
    float* wo   = (float*)wo_p;

    cudaFuncSetAttribute(attn_tc, cudaFuncAttributeMaxDynamicSharedMemorySize,
                         ATT_SMEM);
    cudaFuncSetAttribute(tgemm, cudaFuncAttributeMaxDynamicSharedMemorySize,
                         TG_SMEM);

    // 0) pre-round operands to tf32 (rna)
    {
        int n4;
        n4 = TT * HH / 4;
        round_tf32<<<(n4 + 255) / 256, 256>>>(hidden, hid, n4);
        n4 = HH * QKVW / 4;
        round_tf32<<<(n4 + 255) / 256, 256>>>(w_qkv, wqkv, n4);
        n4 = QSIZE * HH / 4;
        round_tf32<<<(n4 + 255) / 256, 256>>>(w_o, wo, n4);
    }
    // 1) qkv = hid @ wqkv
    {
        dim3 grid(QKVW / BN, TT / BM);
        tgemm<<<grid, 256, TG_SMEM>>>(hid, wqkv, qkv, TT, QKVW, HH);
    }
    // 2) RoPE
    {
        int total = TT * (NHEAD + NKVH) * 64;
        rope_kernel<<<(total + 255) / 256, 256>>>(positions, qkv);
    }
    // 3) attention
    {
        dim3 grid(NHEAD, TT / ABQ);
        attn_tc<<<grid, 256, ATT_SMEM>>>(qkv, attn);
    }
    // 4) out = attn @ wo
    {
        dim3 grid(HH / BN, TT / BM);
        tgemm<<<grid, 256, TG_SMEM>>>(attn, wo, out, TT, HH, QSIZE);
    }
}

// round 7
// speedup vs baseline: 1.1394x; 1.1394x over previous
#include <cuda_runtime.h>
#include <math.h>
#include <stdint.h>

// Problem constants
#define TT    2048
#define HH    4096
#define NHEAD 32
#define NKVH  8
#define HD    128
#define QSIZE 4096          // NHEAD*HD
#define KVSIZE 1024         // NKVH*HD
#define QKVW  6144          // QSIZE + 2*KVSIZE

// Scratch (no cudaMalloc allowed)
__device__ float g_qkv[(size_t)TT * QKVW];     // 48 MB
__device__ float g_attn[(size_t)TT * QSIZE];   // 32 MB
__device__ float g_hid[(size_t)TT * HH];       // 32 MB  (tf32-rounded hidden)
__device__ float g_wqkv[(size_t)HH * QKVW];    // 96 MB  (tf32-rounded w_qkv)
__device__ float g_wo[(size_t)QSIZE * HH];     // 64 MB  (tf32-rounded w_o)

// ---------------------------------------------------------------------------
// Common helpers
// ---------------------------------------------------------------------------
__device__ __forceinline__ float f2tf32(float x) {
    uint32_t u;
    asm("cvt.rna.tf32.f32 %0, %1;" : "=r"(u) : "f"(x));
    return __uint_as_float(u);
}

__device__ __forceinline__ uint32_t smem_u32(const void* p) {
    return (uint32_t)__cvta_generic_to_shared(p);
}

__device__ __forceinline__ void ldsm4(uint32_t& r0, uint32_t& r1, uint32_t& r2,
                                      uint32_t& r3, uint32_t addr) {
    asm volatile("ldmatrix.sync.aligned.m8n8.x4.shared.b16 {%0,%1,%2,%3}, [%4];"
                 : "=r"(r0), "=r"(r1), "=r"(r2), "=r"(r3) : "r"(addr));
}

__device__ __forceinline__ void mma_tf32(float c[4], uint32_t a0, uint32_t a1,
                                         uint32_t a2, uint32_t a3,
                                         uint32_t b0, uint32_t b1) {
    asm volatile(
        "mma.sync.aligned.m16n8k8.row.col.f32.tf32.tf32.f32 "
        "{%0,%1,%2,%3}, {%4,%5,%6,%7}, {%8,%9}, {%0,%1,%2,%3};"
        : "+f"(c[0]), "+f"(c[1]), "+f"(c[2]), "+f"(c[3])
        : "r"(a0), "r"(a1), "r"(a2), "r"(a3), "r"(b0), "r"(b1));
}

__device__ __forceinline__ void cpasync16(uint32_t dst, const void* src) {
    asm volatile("cp.async.cg.shared.global [%0], [%1], 16;"
                 :: "r"(dst), "l"(src));
}

// ---------------------------------------------------------------------------
// Elementwise rna-tf32 rounding pass
// ---------------------------------------------------------------------------
__global__ void round_tf32(const float* __restrict__ in, float* __restrict__ out,
                           int n4) {
    int i = blockIdx.x * blockDim.x + threadIdx.x;
    if (i >= n4) return;
    float4 v = ((const float4*)in)[i];
    v.x = f2tf32(v.x); v.y = f2tf32(v.y);
    v.z = f2tf32(v.z); v.w = f2tf32(v.w);
    ((float4*)out)[i] = v;
}

// ---------------------------------------------------------------------------
// TF32 tensor-core GEMM, cp.async 5-stage pipeline, BK=16.
// C[M,N] = A[M,K] @ B[K,N], row-major; A,B pre-rounded to tf32.
// 128x128x16 CTA tile, 8 warps (2x4), warp tile 64x32.
// A smem [m][k] stride 20 (ldmatrix, conflict-free);
// B smem [k][n] stride 136 (vector fill; direct-LDS fragments, conflict-free).
// CTA raster swizzle: strips of 8 bx share B tiles in L2.
// ---------------------------------------------------------------------------
#define BM 128
#define BN 128
#define BKK 16
#define ASTR 20
#define BSTR 136
#define NST 5
#define STAGE_A (BM * ASTR)            // 2560 floats per A stage
#define STAGE_B (BKK * BSTR)           // 2176 floats per B stage
#define TG_SMEM ((STAGE_A + STAGE_B) * NST * 4)   // 94720 B
#define RGROUP 8

__global__ __launch_bounds__(256) void tgemm(const float* __restrict__ A,
                                             const float* __restrict__ B,
                                             float* __restrict__ C,
                                             int M, int N, int K) {
    extern __shared__ float smp[];
    float* As = smp;                     // [NST][BM][ASTR]
    float* Bs = smp + NST * STAGE_A;     // [NST][BKK][BSTR]

    const int tid  = threadIdx.x;
    const int lane = tid & 31;
    const int wid  = tid >> 5;
    const int mwarp = (wid >> 2) * 64;
    const int nwarp = (wid & 3) * 32;

    // raster swizzle: strips of RGROUP bx spanning all by
    const int flat = blockIdx.y * gridDim.x + blockIdx.x;
    const int strip = flat / (RGROUP * gridDim.y);
    const int rem   = flat % (RGROUP * gridDim.y);
    const int bx = strip * RGROUP + (rem % RGROUP);
    const int by = rem / RGROUP;

    // cp.async mapping: A -> thread (row=tid/2, koff=(tid&1)*8), two 16B chunks
    //                   B -> thread (k=tid/16, n=(tid%16)*8),   two 16B chunks
    const int arow = tid >> 1;
    const int akoff = (tid & 1) * 8;
    const float* Ag = A + (size_t)(by * BM + arow) * K + akoff;
    const uint32_t aDst = smem_u32(&As[arow * ASTR + akoff]);

    const int bk = tid >> 4;
    const int bn = (tid & 15) * 8;
    const float* Bg = B + (size_t)bk * N + bx * BN + bn;
    const uint32_t bDst = smem_u32(&Bs[bk * BSTR + bn]);

    const int KT = K / BKK;

#define ISSUE(kt, s)                                                    \
    {                                                                   \
        const float* a_ = Ag + (kt) * BKK;                              \
        uint32_t ad_ = aDst + (s) * (STAGE_A * 4);                      \
        cpasync16(ad_, a_);                                             \
        cpasync16(ad_ + 16, a_ + 4);                                    \
        const float* b_ = Bg + (size_t)(kt) * BKK * N;                  \
        uint32_t bd_ = bDst + (s) * (STAGE_B * 4);                      \
        cpasync16(bd_, b_);                                             \
        cpasync16(bd_ + 16, b_ + 4);                                    \
        asm volatile("cp.async.commit_group;");                         \
    }

    ISSUE(0, 0);
    ISSUE(1, 1);
    ISSUE(2, 2);
    ISSUE(3, 3);

    float acc[4][4][4];
#pragma unroll
    for (int mi = 0; mi < 4; mi++)
#pragma unroll
        for (int ni = 0; ni < 4; ni++)
#pragma unroll
            for (int r = 0; r < 4; r++) acc[mi][ni][r] = 0.f;

    const uint32_t aFrag0 =
        smem_u32(As) + ((mwarp + (lane & 15)) * ASTR + (lane >> 4) * 4) * 4;
    const float* bFrag0 = Bs + (lane & 3) * BSTR + nwarp + (lane >> 2);

    for (int kt = 0; kt < KT; kt++) {
        asm volatile("cp.async.wait_group 3;");
        __syncthreads();
        if (kt + 4 < KT) ISSUE(kt + 4, (kt + 4) % NST);

        const int s = kt % NST;
        const uint32_t aS = aFrag0 + s * (STAGE_A * 4);
        const float* bS = bFrag0 + s * STAGE_B;

#pragma unroll
        for (int ks = 0; ks < 2; ks++) {
            uint32_t aF[4][4];
#pragma unroll
            for (int mi = 0; mi < 4; mi++)
                ldsm4(aF[mi][0], aF[mi][1], aF[mi][2], aF[mi][3],
                      aS + mi * 16 * ASTR * 4 + ks * 32);
            const float* bRow = bS + ks * 8 * BSTR;
#pragma unroll
            for (int ni = 0; ni < 4; ni++) {
                uint32_t b0 = __float_as_uint(bRow[ni * 8]);
                uint32_t b1 = __float_as_uint(bRow[4 * BSTR + ni * 8]);
#pragma unroll
                for (int mi = 0; mi < 4; mi++)
                    mma_tf32(acc[mi][ni], aF[mi][0], aF[mi][1], aF[mi][2],
                             aF[mi][3], b0, b1);
            }
        }
    }

#pragma unroll
    for (int mi = 0; mi < 4; mi++) {
#pragma unroll
        for (int ni = 0; ni < 4; ni++) {
            int r = by * BM + mwarp + mi * 16 + (lane >> 2);
            int c = bx * BN + nwarp + ni * 8 + (lane & 3) * 2;
            *(float2*)&C[(size_t)r * N + c] =
                make_float2(acc[mi][ni][0], acc[mi][ni][1]);
            *(float2*)&C[(size_t)(r + 8) * N + c] =
                make_float2(acc[mi][ni][2], acc[mi][ni][3]);
        }
    }
#undef ISSUE
}

// ---------------------------------------------------------------------------
// RoPE in-place, fp32 math
// ---------------------------------------------------------------------------
__global__ void rope_kernel(const int* __restrict__ pos, float* __restrict__ qkv) {
    const int total = TT * (NHEAD + NKVH) * 64;
    int idx = blockIdx.x * blockDim.x + threadIdx.x;
    if (idx >= total) return;
    int i = idx & 63;
    int h = (idx >> 6) % (NHEAD + NKVH);
    int t = idx / ((NHEAD + NKVH) * 64);
    int col = (h < NHEAD) ? h * HD : QSIZE + (h - NHEAD) * HD;
    float* p = qkv + (size_t)t * QKVW + col + i;
    float inv = exp2f(-(float)i * 0.2958057710522857f);
    float fr = (float)pos[t] * inv;
    float s, c;
    sincosf(fr, &s, &c);
    float x1 = p[0], x2 = p[64];
    p[0]  = x1 * c - x2 * s;
    p[64] = x2 * c + x1 * s;
}

// ---------------------------------------------------------------------------
// Tensor-core flash attention (tf32), causal, GQA group=4. (unchanged R4)
// ---------------------------------------------------------------------------
#define ABQ  128
#define ABKV 64
#define QSTR 132
#define KSTR 132
#define VSTR 136
#define PSTR 68
#define ATT_SMEM ((ABQ * QSTR + ABKV * KSTR + ABKV * VSTR + ABQ * PSTR) * 4)

__global__ __launch_bounds__(256) void attn_tc(const float* __restrict__ qkv,
                                               float* __restrict__ out) {
    extern __shared__ float sm[];
    float* Qs = sm;                       // [128][QSTR]
    float* Ks = Qs + ABQ * QSTR;          // [64][KSTR]
    float* Vs = Ks + ABKV * KSTR;         // [64][VSTR]
    float* Ps = Vs + ABKV * VSTR;         // [128][PSTR]

    const int h  = blockIdx.x;
    const int qb = gridDim.y - 1 - blockIdx.y;   // heavy tiles first
    const int kvh = h >> 2;
    const int tid = threadIdx.x;
    const int lane = tid & 31;
    const int wid = tid >> 5;
    const int q0 = wid * 16;
    const float qsc = 0.08838834764831845f * 1.4426950408889634f;

    {
        const float* qp = qkv + (size_t)(qb * ABQ) * QKVW + h * HD;
        for (int i = tid; i < ABQ * 32; i += 256) {
            int r = i >> 5, c = (i & 31) * 4;
            float4 v = *(const float4*)(qp + (size_t)r * QKVW + c);
            v.x = f2tf32(v.x * qsc); v.y = f2tf32(v.y * qsc);
            v.z = f2tf32(v.z * qsc); v.w = f2tf32(v.w * qsc);
            *(float4*)(Qs + r * QSTR + c) = v;
        }
    }

    float m0 = -1e30f, m1 = -1e30f, l0 = 0.f, l1 = 0.f;
    float o[16][4];
#pragma unroll
    for (int ni = 0; ni < 16; ni++)
#pragma unroll
        for (int r = 0; r < 4; r++) o[ni][r] = 0.f;

    const uint32_t qA = smem_u32(&Qs[(q0 + (lane & 15)) * QSTR + (lane >> 4) * 4]);
    const uint32_t kB = smem_u32(&Ks[(lane & 7) * KSTR + (lane >> 3) * 4]);
    const uint32_t pA = smem_u32(&Ps[(q0 + (lane & 15)) * PSTR + (lane >> 4) * 4]);

    const int rowg0 = qb * ABQ + q0;
    const int jmax = qb * 2 + 1;

    for (int j = 0; j <= jmax; j++) {
        __syncthreads();
        {
            const float* kp = qkv + (size_t)(j * ABKV) * QKVW + QSIZE + kvh * HD;
            const float* vp = kp + KVSIZE;
            for (int i = tid; i < ABKV * 32; i += 256) {
                int r = i >> 5, c = (i & 31) * 4;
                float4 kk = *(const float4*)(kp + (size_t)r * QKVW + c);
                kk.x = f2tf32(kk.x); kk.y = f2tf32(kk.y);
                kk.z = f2tf32(kk.z); kk.w = f2tf32(kk.w);
                *(float4*)(Ks + r * KSTR + c) = kk;
                float4 vv = *(const float4*)(vp + (size_t)r * QKVW + c);
                vv.x = f2tf32(vv.x); vv.y = f2tf32(vv.y);
                vv.z = f2tf32(vv.z); vv.w = f2tf32(vv.w);
                *(float4*)(Vs + r * VSTR + c) = vv;
            }
        }
        __syncthreads();

        if (j * ABKV <= rowg0 + 15) {
            float sA[8][4];
#pragma unroll
            for (int ni = 0; ni < 8; ni++)
#pragma unroll
                for (int r = 0; r < 4; r++) sA[ni][r] = 0.f;

#pragma unroll
            for (int kc = 0; kc < 8; kc++) {
                uint32_t a0[4], a1[4];
                ldsm4(a0[0], a0[1], a0[2], a0[3], qA + kc * 64);
                ldsm4(a1[0], a1[1], a1[2], a1[3], qA + kc * 64 + 32);
#pragma unroll
                for (int ni = 0; ni < 8; ni++) {
                    uint32_t b[4];
                    ldsm4(b[0], b[1], b[2], b[3],
                          kB + ni * 8 * KSTR * 4 + kc * 64);
                    mma_tf32(sA[ni], a0[0], a0[1], a0[2], a0[3], b[0], b[1]);
                    mma_tf32(sA[ni], a1[0], a1[1], a1[2], a1[3], b[2], b[3]);
                }
            }

            if (j * ABKV + ABKV - 1 > rowg0) {
                int rg = rowg0 + (lane >> 2);
#pragma unroll
                for (int ni = 0; ni < 8; ni++) {
                    int c0 = j * ABKV + ni * 8 + (lane & 3) * 2;
                    if (c0     > rg)     sA[ni][0] = -INFINITY;
                    if (c0 + 1 > rg)     sA[ni][1] = -INFINITY;
                    if (c0     > rg + 8) sA[ni][2] = -INFINITY;
                    if (c0 + 1 > rg + 8) sA[ni][3] = -INFINITY;
                }
            }

            float mx0 = -INFINITY, mx1 = -INFINITY;
#pragma unroll
            for (int ni = 0; ni < 8; ni++) {
                mx0 = fmaxf(mx0, fmaxf(sA[ni][0], sA[ni][1]));
                mx1 = fmaxf(mx1, fmaxf(sA[ni][2], sA[ni][3]));
            }
            mx0 = fmaxf(mx0, __shfl_xor_sync(0xffffffffu, mx0, 1));
            mx0 = fmaxf(mx0, __shfl_xor_sync(0xffffffffu, mx0, 2));
            mx1 = fmaxf(mx1, __shfl_xor_sync(0xffffffffu, mx1, 1));
            mx1 = fmaxf(mx1, __shfl_xor_sync(0xffffffffu, mx1, 2));

            float mn0 = fmaxf(m0, mx0), mn1 = fmaxf(m1, mx1);
            float cr0 = exp2f(m0 - mn0), cr1 = exp2f(m1 - mn1);
            m0 = mn0; m1 = mn1;

            float s0 = 0.f, s1 = 0.f;
#pragma unroll
            for (int ni = 0; ni < 8; ni++) {
                float p0 = exp2f(sA[ni][0] - mn0);
                float p1 = exp2f(sA[ni][1] - mn0);
                float p2 = exp2f(sA[ni][2] - mn1);
                float p3 = exp2f(sA[ni][3] - mn1);
                s0 += p0 + p1;
                s1 += p2 + p3;
                sA[ni][0] = f2tf32(p0); sA[ni][1] = f2tf32(p1);
                sA[ni][2] = f2tf32(p2); sA[ni][3] = f2tf32(p3);
            }
            s0 += __shfl_xor_sync(0xffffffffu, s0, 1);
            s0 += __shfl_xor_sync(0xffffffffu, s0, 2);
            s1 += __shfl_xor_sync(0xffffffffu, s1, 1);
            s1 += __shfl_xor_sync(0xffffffffu, s1, 2);
            l0 = l0 * cr0 + s0;
            l1 = l1 * cr1 + s1;
#pragma unroll
            for (int ni = 0; ni < 16; ni++) {
                o[ni][0] *= cr0; o[ni][1] *= cr0;
                o[ni][2] *= cr1; o[ni][3] *= cr1;
            }

            {
                int rq = q0 + (lane >> 2);
                float* pr0 = &Ps[rq * PSTR + (lane & 3) * 2];
                float* pr1 = &Ps[(rq + 8) * PSTR + (lane & 3) * 2];
#pragma unroll
                for (int ni = 0; ni < 8; ni++) {
                    *(float2*)(pr0 + ni * 8) = make_float2(sA[ni][0], sA[ni][1]);
                    *(float2*)(pr1 + ni * 8) = make_float2(sA[ni][2], sA[ni][3]);
                }
            }
            __syncwarp();

#pragma unroll
            for (int sk = 0; sk < 8; sk++) {
                uint32_t a[4];
                ldsm4(a[0], a[1], a[2], a[3], pA + sk * 32);
                const float* vb = &Vs[(sk * 8 + (lane & 3)) * VSTR + (lane >> 2)];
#pragma unroll
                for (int ni = 0; ni < 16; ni++) {
                    uint32_t b0 = __float_as_uint(vb[ni * 8]);
                    uint32_t b1 = __float_as_uint(vb[4 * VSTR + ni * 8]);
                    mma_tf32(o[ni], a[0], a[1], a[2], a[3], b0, b1);
                }
            }
            __syncwarp();
        }
    }

    float i0 = 1.f / l0, i1 = 1.f / l1;
    int rg = qb * ABQ + q0 + (lane >> 2);
    float* op = out + (size_t)rg * QSIZE + h * HD + (lane & 3) * 2;
#pragma unroll
    for (int ni = 0; ni < 16; ni++) {
        *(float2*)(op + ni * 8) =
            make_float2(f2tf32(o[ni][0] * i0), f2tf32(o[ni][1] * i0));
        *(float2*)(op + (size_t)8 * QSIZE + ni * 8) =
            make_float2(f2tf32(o[ni][2] * i1), f2tf32(o[ni][3] * i1));
    }
}

// ---------------------------------------------------------------------------
extern "C" void kernel_launch(void* const* d_in, const int* in_sizes, int n_in,
                              void* d_out, int out_size) {
    const int*   positions = (const int*)d_in[0];
    const float* hidden    = (const float*)d_in[1];
    const float* w_qkv     = (const float*)d_in[2];
    const float* w_o       = (const float*)d_in[3];
    float*       out       = (float*)d_out;

    void *qkv_p, *attn_p, *hid_p, *wqkv_p, *wo_p;
    cudaGetSymbolAddress(&qkv_p, g_qkv);
    cudaGetSymbolAddress(&attn_p, g_attn);
    cudaGetSymbolAddress(&hid_p, g_hid);
    cudaGetSymbolAddress(&wqkv_p, g_wqkv);
    cudaGetSymbolAddress(&wo_p, g_wo);
    float* qkv  = (float*)qkv_p;
    float* attn = (float*)attn_p;
    float* hid  = (float*)hid_p;
    float* wqkv = (float*)wqkv_p;
    float* wo   = (float*)wo_p;

    cudaFuncSetAttribute(attn_tc, cudaFuncAttributeMaxDynamicSharedMemorySize,
                         ATT_SMEM);
    cudaFuncSetAttribute(tgemm, cudaFuncAttributeMaxDynamicSharedMemorySize,
                         TG_SMEM);

    // 0) pre-round operands to tf32 (rna)
    {
        int n4;
        n4 = TT * HH / 4;
        round_tf32<<<(n4 + 255) / 256, 256>>>(hidden, hid, n4);
        n4 = HH * QKVW / 4;
        round_tf32<<<(n4 + 255) / 256, 256>>>(w_qkv, wqkv, n4);
        n4 = QSIZE * HH / 4;
        round_tf32<<<(n4 + 255) / 256, 256>>>(w_o, wo, n4);
    }
    // 1) qkv = hid @ wqkv
    {
        dim3 grid(QKVW / BN, TT / BM);
        tgemm<<<grid, 256, TG_SMEM>>>(hid, wqkv, qkv, TT, QKVW, HH);
    }
    // 2) RoPE
    {
        int total = TT * (NHEAD + NKVH) * 64;
        rope_kernel<<<(total + 255) / 256, 256>>>(positions, qkv);
    }
    // 3) attention
    {
        dim3 grid(NHEAD, TT / ABQ);
        attn_tc<<<grid, 256, ATT_SMEM>>>(qkv, attn);
    }
    // 4) out = attn @ wo
    {
        dim3 grid(HH / BN, TT / BM);
        tgemm<<<grid, 256, TG_SMEM>>>(attn, wo, out, TT, HH, QSIZE);
    }
}

// round 8
// speedup vs baseline: 2.0161x; 1.7694x over previous
#include <cuda_runtime.h>
#include <cuda_fp16.h>
#include <math.h>
#include <stdint.h>

// Problem constants
#define TT    2048
#define HH    4096
#define NHEAD 32
#define NKVH  8
#define HD    128
#define QSIZE 4096          // NHEAD*HD
#define KVSIZE 1024         // NKVH*HD
#define QKVW  6144          // QSIZE + 2*KVSIZE

// Scratch (no cudaMalloc allowed)
__device__ float  g_qkv[(size_t)TT * QKVW];      // 48 MB (fp32 qkv)
__device__ __half g_attn16[(size_t)TT * QSIZE];  // 16 MB (half attn out)
__device__ __half g_hid16[(size_t)TT * HH];      // 16 MB (half hidden)
__device__ __half g_wqkvT[(size_t)QKVW * HH];    // 48 MB (w_qkv^T half)
__device__ __half g_woT[(size_t)HH * QSIZE];     // 32 MB (w_o^T half)

// ---------------------------------------------------------------------------
// Common helpers
// ---------------------------------------------------------------------------
__device__ __forceinline__ float f2tf32(float x) {
    uint32_t u;
    asm("cvt.rna.tf32.f32 %0, %1;" : "=r"(u) : "f"(x));
    return __uint_as_float(u);
}

__device__ __forceinline__ uint32_t smem_u32(const void* p) {
    return (uint32_t)__cvta_generic_to_shared(p);
}

__device__ __forceinline__ void ldsm4(uint32_t& r0, uint32_t& r1, uint32_t& r2,
                                      uint32_t& r3, uint32_t addr) {
    asm volatile("ldmatrix.sync.aligned.m8n8.x4.shared.b16 {%0,%1,%2,%3}, [%4];"
                 : "=r"(r0), "=r"(r1), "=r"(r2), "=r"(r3) : "r"(addr));
}

__device__ __forceinline__ void mma_tf32(float c[4], uint32_t a0, uint32_t a1,
                                         uint32_t a2, uint32_t a3,
                                         uint32_t b0, uint32_t b1) {
    asm volatile(
        "mma.sync.aligned.m16n8k8.row.col.f32.tf32.tf32.f32 "
        "{%0,%1,%2,%3}, {%4,%5,%6,%7}, {%8,%9}, {%0,%1,%2,%3};"
        : "+f"(c[0]), "+f"(c[1]), "+f"(c[2]), "+f"(c[3])
        : "r"(a0), "r"(a1), "r"(a2), "r"(a3), "r"(b0), "r"(b1));
}

__device__ __forceinline__ void mma_f16(float c[4], uint32_t a0, uint32_t a1,
                                        uint32_t a2, uint32_t a3,
                                        uint32_t b0, uint32_t b1) {
    asm volatile(
        "mma.sync.aligned.m16n8k16.row.col.f32.f16.f16.f32 "
        "{%0,%1,%2,%3}, {%4,%5,%6,%7}, {%8,%9}, {%0,%1,%2,%3};"
        : "+f"(c[0]), "+f"(c[1]), "+f"(c[2]), "+f"(c[3])
        : "r"(a0), "r"(a1), "r"(a2), "r"(a3), "r"(b0), "r"(b1));
}

__device__ __forceinline__ void cpasync16(uint32_t dst, const void* src) {
    asm volatile("cp.async.cg.shared.global [%0], [%1], 16;"
                 :: "r"(dst), "l"(src));
}

// ---------------------------------------------------------------------------
// Pre-passes: fp32 -> half convert; fp32 [R][C] -> half [C][R] transpose
// ---------------------------------------------------------------------------
__global__ void conv_half(const float* __restrict__ in, __half* __restrict__ out,
                          int n4) {
    int i = blockIdx.x * blockDim.x + threadIdx.x;
    if (i >= n4) return;
    float4 v = ((const float4*)in)[i];
    __half2 h0 = __floats2half2_rn(v.x, v.y);
    __half2 h1 = __floats2half2_rn(v.z, v.w);
    ((uint2*)out)[i] = make_uint2(*(uint32_t*)&h0, *(uint32_t*)&h1);
}

__global__ void transpose_half(const float* __restrict__ in,
                               __half* __restrict__ out, int R, int C) {
    __shared__ float t[32][33];
    int tx = threadIdx.x, ty = threadIdx.y;
    int x = blockIdx.x * 32 + tx;
#pragma unroll
    for (int j = 0; j < 32; j += 8)
        t[ty + j][tx] = in[(size_t)(blockIdx.y * 32 + ty + j) * C + x];
    __syncthreads();
    int x2 = blockIdx.y * 32 + tx;
#pragma unroll
    for (int j = 0; j < 32; j += 8)
        out[(size_t)(blockIdx.x * 32 + ty + j) * R + x2] =
            __float2half_rn(t[tx][ty + j]);
}

// ---------------------------------------------------------------------------
// FP16 tensor-core GEMM, cp.async 4-stage pipeline, BK=32 halves.
// C[M,N](f32) = A[M,K](h) @ Bt[N,K](h)^T ; both operands K-major.
// 128x128x32 CTA tile, 8 warps (2x4), warp tile 64x32, mma.m16n8k16.
// smem rows stride 40 halves (80B) -> all ldmatrix phases conflict-free.
// ---------------------------------------------------------------------------
#define BM 128
#define BN 128
#define HAS 40                          // halves per smem row
#define NST 4
#define STAGE_H (128 * HAS)             // halves per (A or B) stage
#define TG_SMEM (NST * 2 * STAGE_H * 2) // 81920 B
#define RGROUP 8

__global__ __launch_bounds__(256, 2) void hgemm(const __half* __restrict__ A,
                                                const __half* __restrict__ Bt,
                                                float* __restrict__ C,
                                                int M, int N, int K) {
    extern __shared__ __half smh[];
    __half* As = smh;                     // [NST][128][HAS]
    __half* Bs = smh + NST * STAGE_H;     // [NST][128][HAS]

    const int tid  = threadIdx.x;
    const int lane = tid & 31;
    const int wid  = tid >> 5;
    const int mwarp = (wid >> 2) * 64;
    const int nwarp = (wid & 3) * 32;

    // raster swizzle: strips of RGROUP bx spanning all by
    const int flat = blockIdx.y * gridDim.x + blockIdx.x;
    const int strip = flat / (RGROUP * gridDim.y);
    const int rem   = flat % (RGROUP * gridDim.y);
    const int bx = strip * RGROUP + (rem % RGROUP);
    const int by = rem / RGROUP;

    // fill mapping: thread t -> row t/2, two 16B chunks at halves (t&1)*16, +8
    const int frow = tid >> 1;
    const int foff = (tid & 1) * 16;
    const __half* Ag = A + (size_t)(by * BM + frow) * K + foff;
    const __half* Bg = Bt + (size_t)(bx * BN + frow) * K + foff;
    const uint32_t aDst = smem_u32(&As[frow * HAS + foff]);
    const uint32_t bDst = smem_u32(&Bs[frow * HAS + foff]);

    const int KT = K / 32;

#define ISSUE(kt, s)                                                    \
    {                                                                   \
        const __half* a_ = Ag + (kt) * 32;                              \
        const __half* b_ = Bg + (kt) * 32;                              \
        uint32_t ad_ = aDst + (s) * (STAGE_H * 2);                      \
        uint32_t bd_ = bDst + (s) * (STAGE_H * 2);                      \
        cpasync16(ad_, a_);                                             \
        cpasync16(ad_ + 16, a_ + 8);                                    \
        cpasync16(bd_, b_);                                             \
        cpasync16(bd_ + 16, b_ + 8);                                    \
        asm volatile("cp.async.commit_group;");                         \
    }

    ISSUE(0, 0);
    ISSUE(1, 1);
    ISSUE(2, 2);

    float acc[4][4][4];
#pragma unroll
    for (int mi = 0; mi < 4; mi++)
#pragma unroll
        for (int ni = 0; ni < 4; ni++)
#pragma unroll
            for (int r = 0; r < 4; r++) acc[mi][ni][r] = 0.f;

    // ldmatrix lane addresses (bytes)
    const uint32_t aAddr =
        smem_u32(As) + ((mwarp + (lane & 15)) * HAS + (lane >> 4) * 8) * 2;
    const uint32_t bAddr =
        smem_u32(Bs) +
        ((nwarp + ((lane >> 4) << 3) + (lane & 7)) * HAS + ((lane >> 3) & 1) * 8) * 2;

    for (int kt = 0; kt < KT; kt++) {
        asm volatile("cp.async.wait_group 2;");
        __syncthreads();
        if (kt + 3 < KT) ISSUE(kt + 3, (kt + 3) % NST);

        const int s = kt % NST;
        const uint32_t aS = aAddr + s * (STAGE_H * 2);
        const uint32_t bS = bAddr + s * (STAGE_H * 2);

#pragma unroll
        for (int ks = 0; ks < 2; ks++) {
            uint32_t aF[4][4];
#pragma unroll
            for (int mi = 0; mi < 4; mi++)
                ldsm4(aF[mi][0], aF[mi][1], aF[mi][2], aF[mi][3],
                      aS + (mi * 16 * HAS + ks * 16) * 2);
            uint32_t bF[2][4];
#pragma unroll
            for (int ng = 0; ng < 2; ng++)
                ldsm4(bF[ng][0], bF[ng][1], bF[ng][2], bF[ng][3],
                      bS + (ng * 16 * HAS + ks * 16) * 2);
#pragma unroll
            for (int mi = 0; mi < 4; mi++) {
                mma_f16(acc[mi][0], aF[mi][0], aF[mi][1], aF[mi][2], aF[mi][3],
                        bF[0][0], bF[0][1]);
                mma_f16(acc[mi][1], aF[mi][0], aF[mi][1], aF[mi][2], aF[mi][3],
                        bF[0][2], bF[0][3]);
                mma_f16(acc[mi][2], aF[mi][0], aF[mi][1], aF[mi][2], aF[mi][3],
                        bF[1][0], bF[1][1]);
                mma_f16(acc[mi][3], aF[mi][0], aF[mi][1], aF[mi][2], aF[mi][3],
                        bF[1][2], bF[1][3]);
            }
        }
    }

#pragma unroll
    for (int mi = 0; mi < 4; mi++) {
#pragma unroll
        for (int ni = 0; ni < 4; ni++) {
            int r = by * BM + mwarp + mi * 16 + (lane >> 2);
            int c = bx * BN + nwarp + ni * 8 + (lane & 3) * 2;
            *(float2*)&C[(size_t)r * N + c] =
                make_float2(acc[mi][ni][0], acc[mi][ni][1]);
            *(float2*)&C[(size_t)(r + 8) * N + c] =
                make_float2(acc[mi][ni][2], acc[mi][ni][3]);
        }
    }
#undef ISSUE
}

// ---------------------------------------------------------------------------
// RoPE in-place, fp32 math
// ---------------------------------------------------------------------------
__global__ void rope_kernel(const int* __restrict__ pos, float* __restrict__ qkv) {
    const int total = TT * (NHEAD + NKVH) * 64;
    int idx = blockIdx.x * blockDim.x + threadIdx.x;
    if (idx >= total) return;
    int i = idx & 63;
    int h = (idx >> 6) % (NHEAD + NKVH);
    int t = idx / ((NHEAD + NKVH) * 64);
    int col = (h < NHEAD) ? h * HD : QSIZE + (h - NHEAD) * HD;
    float* p = qkv + (size_t)t * QKVW + col + i;
    float inv = exp2f(-(float)i * 0.2958057710522857f);
    float fr = (float)pos[t] * inv;
    float s, c;
    sincosf(fr, &s, &c);
    float x1 = p[0], x2 = p[64];
    p[0]  = x1 * c - x2 * s;
    p[64] = x2 * c + x1 * s;
}

// ---------------------------------------------------------------------------
// Tensor-core flash attention (tf32), causal, GQA group=4.
// Unchanged from R4 except: output written as half (feeds fp16 GEMM2).
// ---------------------------------------------------------------------------
#define ABQ  128
#define ABKV 64
#define QSTR 132
#define KSTR 132
#define VSTR 136
#define PSTR 68
#define ATT_SMEM ((ABQ * QSTR + ABKV * KSTR + ABKV * VSTR + ABQ * PSTR) * 4)

__global__ __launch_bounds__(256) void attn_tc(const float* __restrict__ qkv,
                                               __half* __restrict__ out) {
    extern __shared__ float sm[];
    float* Qs = sm;                       // [128][QSTR]
    float* Ks = Qs + ABQ * QSTR;          // [64][KSTR]
    float* Vs = Ks + ABKV * KSTR;         // [64][VSTR]
    float* Ps = Vs + ABKV * VSTR;         // [128][PSTR]

    const int h  = blockIdx.x;
    const int qb = gridDim.y - 1 - blockIdx.y;   // heavy tiles first
    const int kvh = h >> 2;
    const int tid = threadIdx.x;
    const int lane = tid & 31;
    const int wid = tid >> 5;
    const int q0 = wid * 16;
    const float qsc = 0.08838834764831845f * 1.4426950408889634f;

    {
        const float* qp = qkv + (size_t)(qb * ABQ) * QKVW + h * HD;
        for (int i = tid; i < ABQ * 32; i += 256) {
            int r = i >> 5, c = (i & 31) * 4;
            float4 v = *(const float4*)(qp + (size_t)r * QKVW + c);
            v.x = f2tf32(v.x * qsc); v.y = f2tf32(v.y * qsc);
            v.z = f2tf32(v.z * qsc); v.w = f2tf32(v.w * qsc);
            *(float4*)(Qs + r * QSTR + c) = v;
        }
    }

    float m0 = -1e30f, m1 = -1e30f, l0 = 0.f, l1 = 0.f;
    float o[16][4];
#pragma unroll
    for (int ni = 0; ni < 16; ni++)
#pragma unroll
        for (int r = 0; r < 4; r++) o[ni][r] = 0.f;

    const uint32_t qA = smem_u32(&Qs[(q0 + (lane & 15)) * QSTR + (lane >> 4) * 4]);
    const uint32_t kB = smem_u32(&Ks[(lane & 7) * KSTR + (lane >> 3) * 4]);
    const uint32_t pA = smem_u32(&Ps[(q0 + (lane & 15)) * PSTR + (lane >> 4) * 4]);

    const int rowg0 = qb * ABQ + q0;
    const int jmax = qb * 2 + 1;

    for (int j = 0; j <= jmax; j++) {
        __syncthreads();
        {
            const float* kp = qkv + (size_t)(j * ABKV) * QKVW + QSIZE + kvh * HD;
            const float* vp = kp + KVSIZE;
            for (int i = tid; i < ABKV * 32; i += 256) {
                int r = i >> 5, c = (i & 31) * 4;
                float4 kk = *(const float4*)(kp + (size_t)r * QKVW + c);
                kk.x = f2tf32(kk.x); kk.y = f2tf32(kk.y);
                kk.z = f2tf32(kk.z); kk.w = f2tf32(kk.w);
                *(float4*)(Ks + r * KSTR + c) = kk;
                float4 vv = *(const float4*)(vp + (size_t)r * QKVW + c);
                vv.x = f2tf32(vv.x); vv.y = f2tf32(vv.y);
                vv.z = f2tf32(vv.z); vv.w = f2tf32(vv.w);
                *(float4*)(Vs + r * VSTR + c) = vv;
            }
        }
        __syncthreads();

        if (j * ABKV <= rowg0 + 15) {
            float sA[8][4];
#pragma unroll
            for (int ni = 0; ni < 8; ni++)
#pragma unroll
                for (int r = 0; r < 4; r++) sA[ni][r] = 0.f;

#pragma unroll
            for (int kc = 0; kc < 8; kc++) {
                uint32_t a0[4], a1[4];
                ldsm4(a0[0], a0[1], a0[2], a0[3], qA + kc * 64);
                ldsm4(a1[0], a1[1], a1[2], a1[3], qA + kc * 64 + 32);
#pragma unroll
                for (int ni = 0; ni < 8; ni++) {
                    uint32_t b[4];
                    ldsm4(b[0], b[1], b[2], b[3],
                          kB + ni * 8 * KSTR * 4 + kc * 64);
                    mma_tf32(sA[ni], a0[0], a0[1], a0[2], a0[3], b[0], b[1]);
                    mma_tf32(sA[ni], a1[0], a1[1], a1[2], a1[3], b[2], b[3]);
                }
            }

            if (j * ABKV + ABKV - 1 > rowg0) {
                int rg = rowg0 + (lane >> 2);
#pragma unroll
                for (int ni = 0; ni < 8; ni++) {
                    int c0 = j * ABKV + ni * 8 + (lane & 3) * 2;
                    if (c0     > rg)     sA[ni][0] = -INFINITY;
                    if (c0 + 1 > rg)     sA[ni][1] = -INFINITY;
                    if (c0     > rg + 8) sA[ni][2] = -INFINITY;
                    if (c0 + 1 > rg + 8) sA[ni][3] = -INFINITY;
                }
            }

            float mx0 = -INFINITY, mx1 = -INFINITY;
#pragma unroll
            for (int ni = 0; ni < 8; ni++) {
                mx0 = fmaxf(mx0, fmaxf(sA[ni][0], sA[ni][1]));
                mx1 = fmaxf(mx1, fmaxf(sA[ni][2], sA[ni][3]));
            }
            mx0 = fmaxf(mx0, __shfl_xor_sync(0xffffffffu, mx0, 1));
            mx0 = fmaxf(mx0, __shfl_xor_sync(0xffffffffu, mx0, 2));
            mx1 = fmaxf(mx1, __shfl_xor_sync(0xffffffffu, mx1, 1));
            mx1 = fmaxf(mx1, __shfl_xor_sync(0xffffffffu, mx1, 2));

            float mn0 = fmaxf(m0, mx0), mn1 = fmaxf(m1, mx1);
            float cr0 = exp2f(m0 - mn0), cr1 = exp2f(m1 - mn1);
            m0 = mn0; m1 = mn1;

            float s0 = 0.f, s1 = 0.f;
#pragma unroll
            for (int ni = 0; ni < 8; ni++) {
                float p0 = exp2f(sA[ni][0] - mn0);
                float p1 = exp2f(sA[ni][1] - mn0);
                float p2 = exp2f(sA[ni][2] - mn1);
                float p3 = exp2f(sA[ni][3] - mn1);
                s0 += p0 + p1;
                s1 += p2 + p3;
                sA[ni][0] = f2tf32(p0); sA[ni][1] = f2tf32(p1);
                sA[ni][2] = f2tf32(p2); sA[ni][3] = f2tf32(p3);
            }
            s0 += __shfl_xor_sync(0xffffffffu, s0, 1);
            s0 += __shfl_xor_sync(0xffffffffu, s0, 2);
            s1 += __shfl_xor_sync(0xffffffffu, s1, 1);
            s1 += __shfl_xor_sync(0xffffffffu, s1, 2);
            l0 = l0 * cr0 + s0;
            l1 = l1 * cr1 + s1;
#pragma unroll
            for (int ni = 0; ni < 16; ni++) {
                o[ni][0] *= cr0; o[ni][1] *= cr0;
                o[ni][2] *= cr1; o[ni][3] *= cr1;
            }

            {
                int rq = q0 + (lane >> 2);
                float* pr0 = &Ps[rq * PSTR + (lane & 3) * 2];
                float* pr1 = &Ps[(rq + 8) * PSTR + (lane & 3) * 2];
#pragma unroll
                for (int ni = 0; ni < 8; ni++) {
                    *(float2*)(pr0 + ni * 8) = make_float2(sA[ni][0], sA[ni][1]);
                    *(float2*)(pr1 + ni * 8) = make_float2(sA[ni][2], sA[ni][3]);
                }
            }
            __syncwarp();

#pragma unroll
            for (int sk = 0; sk < 8; sk++) {
                uint32_t a[4];
                ldsm4(a[0], a[1], a[2], a[3], pA + sk * 32);
                const float* vb = &Vs[(sk * 8 + (lane & 3)) * VSTR + (lane >> 2)];
#pragma unroll
                for (int ni = 0; ni < 16; ni++) {
                    uint32_t b0 = __float_as_uint(vb[ni * 8]);
                    uint32_t b1 = __float_as_uint(vb[4 * VSTR + ni * 8]);
                    mma_tf32(o[ni], a[0], a[1], a[2], a[3], b0, b1);
                }
            }
            __syncwarp();
        }
    }

    // normalize, write half (feeds fp16 GEMM2 A-side)
    float i0 = 1.f / l0, i1 = 1.f / l1;
    int rg = qb * ABQ + q0 + (lane >> 2);
    __half* op = out + (size_t)rg * QSIZE + h * HD + (lane & 3) * 2;
#pragma unroll
    for (int ni = 0; ni < 16; ni++) {
        *(__half2*)(op + ni * 8) = __floats2half2_rn(o[ni][0] * i0, o[ni][1] * i0);
        *(__half2*)(op + (size_t)8 * QSIZE + ni * 8) =
            __floats2half2_rn(o[ni][2] * i1, o[ni][3] * i1);
    }
}

// ---------------------------------------------------------------------------
extern "C" void kernel_launch(void* const* d_in, const int* in_sizes, int n_in,
                              void* d_out, int out_size) {
    const int*   positions = (const int*)d_in[0];
    const float* hidden    = (const float*)d_in[1];
    const float* w_qkv     = (const float*)d_in[2];
    const float* w_o       = (const float*)d_in[3];
    float*       out       = (float*)d_out;

    void *qkv_p, *attn_p, *hid_p, *wqkvT_p, *woT_p;
    cudaGetSymbolAddress(&qkv_p, g_qkv);
    cudaGetSymbolAddress(&attn_p, g_attn16);
    cudaGetSymbolAddress(&hid_p, g_hid16);
    cudaGetSymbolAddress(&wqkvT_p, g_wqkvT);
    cudaGetSymbolAddress(&woT_p, g_woT);
    float*  qkv    = (float*)qkv_p;
    __half* attn16 = (__half*)attn_p;
    __half* hid16  = (__half*)hid_p;
    __half* wqkvT  = (__half*)wqkvT_p;
    __half* woT    = (__half*)woT_p;

    cudaFuncSetAttribute(attn_tc, cudaFuncAttributeMaxDynamicSharedMemorySize,
                         ATT_SMEM);
    cudaFuncSetAttribute(hgemm, cudaFuncAttributeMaxDynamicSharedMemorySize,
                         TG_SMEM);

    // 0) pre-passes: hidden -> half; weights -> transposed half [N][K]
    {
        int n4 = TT * HH / 4;
        conv_half<<<(n4 + 255) / 256, 256>>>(hidden, hid16, n4);
        dim3 tb(32, 8);
        transpose_half<<<dim3(QKVW / 32, HH / 32), tb>>>(w_qkv, wqkvT, HH, QKVW);
        transpose_half<<<dim3(HH / 32, QSIZE / 32), tb>>>(w_o, woT, QSIZE, HH);
    }
    // 1) qkv = hid @ w_qkv  (fp16 TC)
    {
        dim3 grid(QKVW / BN, TT / BM);
        hgemm<<<grid, 256, TG_SMEM>>>(hid16, wqkvT, qkv, TT, QKVW, HH);
    }
    // 2) RoPE
    {
        int total = TT * (NHEAD + NKVH) * 64;
        rope_kernel<<<(total + 255) / 256, 256>>>(positions, qkv);
    }
    // 3) attention (tf32 TC), half output
    {
        dim3 grid(NHEAD, TT / ABQ);
        attn_tc<<<grid, 256, ATT_SMEM>>>(qkv, attn16);
    }
    // 4) out = attn @ w_o  (fp16 TC)
    {
        dim3 grid(HH / BN, TT / BM);
        hgemm<<<grid, 256, TG_SMEM>>>(attn16, woT, out, TT, HH, QSIZE);
    }
}

// round 9
// speedup vs baseline: 2.3018x; 1.1417x over previous
#include <cuda_runtime.h>
#include <cuda_fp16.h>
#include <math.h>
#include <stdint.h>

// Problem constants
#define TT    2048
#define HH    4096
#define NHEAD 32
#define NKVH  8
#define HD    128
#define QSIZE 4096          // NHEAD*HD
#define KVSIZE 1024         // NKVH*HD
#define QKVW  6144          // QSIZE + 2*KVSIZE

// Scratch (no cudaMalloc allowed)
__device__ float  g_qkv[(size_t)TT * QKVW];      // 48 MB (fp32 qkv)
__device__ __half g_attn16[(size_t)TT * QSIZE];  // 16 MB (half attn out)
__device__ __half g_hid16[(size_t)TT * HH];      // 16 MB (half hidden)
__device__ __half g_wqkvT[(size_t)QKVW * HH];    // 48 MB (w_qkv^T half)
__device__ __half g_woT[(size_t)HH * QSIZE];     // 32 MB (w_o^T half)

// ---------------------------------------------------------------------------
// Common helpers
// ---------------------------------------------------------------------------
__device__ __forceinline__ uint32_t smem_u32(const void* p) {
    return (uint32_t)__cvta_generic_to_shared(p);
}

__device__ __forceinline__ void ldsm4(uint32_t& r0, uint32_t& r1, uint32_t& r2,
                                      uint32_t& r3, uint32_t addr) {
    asm volatile("ldmatrix.sync.aligned.m8n8.x4.shared.b16 {%0,%1,%2,%3}, [%4];"
                 : "=r"(r0), "=r"(r1), "=r"(r2), "=r"(r3) : "r"(addr));
}

__device__ __forceinline__ void ldsm4t(uint32_t& r0, uint32_t& r1, uint32_t& r2,
                                       uint32_t& r3, uint32_t addr) {
    asm volatile(
        "ldmatrix.sync.aligned.m8n8.x4.trans.shared.b16 {%0,%1,%2,%3}, [%4];"
        : "=r"(r0), "=r"(r1), "=r"(r2), "=r"(r3) : "r"(addr));
}

__device__ __forceinline__ void mma_f16(float c[4], uint32_t a0, uint32_t a1,
                                        uint32_t a2, uint32_t a3,
                                        uint32_t b0, uint32_t b1) {
    asm volatile(
        "mma.sync.aligned.m16n8k16.row.col.f32.f16.f16.f32 "
        "{%0,%1,%2,%3}, {%4,%5,%6,%7}, {%8,%9}, {%0,%1,%2,%3};"
        : "+f"(c[0]), "+f"(c[1]), "+f"(c[2]), "+f"(c[3])
        : "r"(a0), "r"(a1), "r"(a2), "r"(a3), "r"(b0), "r"(b1));
}

__device__ __forceinline__ void cpasync16(uint32_t dst, const void* src) {
    asm volatile("cp.async.cg.shared.global [%0], [%1], 16;"
                 :: "r"(dst), "l"(src));
}

// ---------------------------------------------------------------------------
// Pre-passes: fp32 -> half convert; fp32 [R][C] -> half [C][R] transpose
// ---------------------------------------------------------------------------
__global__ void conv_half(const float* __restrict__ in, __half* __restrict__ out,
                          int n4) {
    int i = blockIdx.x * blockDim.x + threadIdx.x;
    if (i >= n4) return;
    float4 v = ((const float4*)in)[i];
    __half2 h0 = __floats2half2_rn(v.x, v.y);
    __half2 h1 = __floats2half2_rn(v.z, v.w);
    ((uint2*)out)[i] = make_uint2(*(uint32_t*)&h0, *(uint32_t*)&h1);
}

__global__ void transpose_half(const float* __restrict__ in,
                               __half* __restrict__ out, int R, int C) {
    __shared__ float t[32][33];
    int tx = threadIdx.x, ty = threadIdx.y;
    int x = blockIdx.x * 32 + tx;
#pragma unroll
    for (int j = 0; j < 32; j += 8)
        t[ty + j][tx] = in[(size_t)(blockIdx.y * 32 + ty + j) * C + x];
    __syncthreads();
    int x2 = blockIdx.y * 32 + tx;
#pragma unroll
    for (int j = 0; j < 32; j += 8)
        out[(size_t)(blockIdx.x * 32 + ty + j) * R + x2] =
            __float2half_rn(t[tx][ty + j]);
}

// ---------------------------------------------------------------------------
// FP16 tensor-core GEMM, cp.async 4-stage pipeline, BK=32 halves. (R8)
// ---------------------------------------------------------------------------
#define BM 128
#define BN 128
#define HAS 40                          // halves per smem row
#define NST 4
#define STAGE_H (128 * HAS)             // halves per (A or B) stage
#define TG_SMEM (NST * 2 * STAGE_H * 2) // 81920 B
#define RGROUP 8

__global__ __launch_bounds__(256, 2) void hgemm(const __half* __restrict__ A,
                                                const __half* __restrict__ Bt,
                                                float* __restrict__ C,
                                                int M, int N, int K) {
    extern __shared__ __half smh[];
    __half* As = smh;                     // [NST][128][HAS]
    __half* Bs = smh + NST * STAGE_H;     // [NST][128][HAS]

    const int tid  = threadIdx.x;
    const int lane = tid & 31;
    const int wid  = tid >> 5;
    const int mwarp = (wid >> 2) * 64;
    const int nwarp = (wid & 3) * 32;

    const int flat = blockIdx.y * gridDim.x + blockIdx.x;
    const int strip = flat / (RGROUP * gridDim.y);
    const int rem   = flat % (RGROUP * gridDim.y);
    const int bx = strip * RGROUP + (rem % RGROUP);
    const int by = rem / RGROUP;

    const int frow = tid >> 1;
    const int foff = (tid & 1) * 16;
    const __half* Ag = A + (size_t)(by * BM + frow) * K + foff;
    const __half* Bg = Bt + (size_t)(bx * BN + frow) * K + foff;
    const uint32_t aDst = smem_u32(&As[frow * HAS + foff]);
    const uint32_t bDst = smem_u32(&Bs[frow * HAS + foff]);

    const int KT = K / 32;

#define ISSUE(kt, s)                                                    \
    {                                                                   \
        const __half* a_ = Ag + (kt) * 32;                              \
        const __half* b_ = Bg + (kt) * 32;                              \
        uint32_t ad_ = aDst + (s) * (STAGE_H * 2);                      \
        uint32_t bd_ = bDst + (s) * (STAGE_H * 2);                      \
        cpasync16(ad_, a_);                                             \
        cpasync16(ad_ + 16, a_ + 8);                                    \
        cpasync16(bd_, b_);                                             \
        cpasync16(bd_ + 16, b_ + 8);                                    \
        asm volatile("cp.async.commit_group;");                         \
    }

    ISSUE(0, 0);
    ISSUE(1, 1);
    ISSUE(2, 2);

    float acc[4][4][4];
#pragma unroll
    for (int mi = 0; mi < 4; mi++)
#pragma unroll
        for (int ni = 0; ni < 4; ni++)
#pragma unroll
            for (int r = 0; r < 4; r++) acc[mi][ni][r] = 0.f;

    const uint32_t aAddr =
        smem_u32(As) + ((mwarp + (lane & 15)) * HAS + (lane >> 4) * 8) * 2;
    const uint32_t bAddr =
        smem_u32(Bs) +
        ((nwarp + ((lane >> 4) << 3) + (lane & 7)) * HAS + ((lane >> 3) & 1) * 8) * 2;

    for (int kt = 0; kt < KT; kt++) {
        asm volatile("cp.async.wait_group 2;");
        __syncthreads();
        if (kt + 3 < KT) ISSUE(kt + 3, (kt + 3) % NST);

        const int s = kt % NST;
        const uint32_t aS = aAddr + s * (STAGE_H * 2);
        const uint32_t bS = bAddr + s * (STAGE_H * 2);

#pragma unroll
        for (int ks = 0; ks < 2; ks++) {
            uint32_t aF[4][4];
#pragma unroll
            for (int mi = 0; mi < 4; mi++)
                ldsm4(aF[mi][0], aF[mi][1], aF[mi][2], aF[mi][3],
                      aS + (mi * 16 * HAS + ks * 16) * 2);
            uint32_t bF[2][4];
#pragma unroll
            for (int ng = 0; ng < 2; ng++)
                ldsm4(bF[ng][0], bF[ng][1], bF[ng][2], bF[ng][3],
                      bS + (ng * 16 * HAS + ks * 16) * 2);
#pragma unroll
            for (int mi = 0; mi < 4; mi++) {
                mma_f16(acc[mi][0], aF[mi][0], aF[mi][1], aF[mi][2], aF[mi][3],
                        bF[0][0], bF[0][1]);
                mma_f16(acc[mi][1], aF[mi][0], aF[mi][1], aF[mi][2], aF[mi][3],
                        bF[0][2], bF[0][3]);
                mma_f16(acc[mi][2], aF[mi][0], aF[mi][1], aF[mi][2], aF[mi][3],
                        bF[1][0], bF[1][1]);
                mma_f16(acc[mi][3], aF[mi][0], aF[mi][1], aF[mi][2], aF[mi][3],
                        bF[1][2], bF[1][3]);
            }
        }
    }

#pragma unroll
    for (int mi = 0; mi < 4; mi++) {
#pragma unroll
        for (int ni = 0; ni < 4; ni++) {
            int r = by * BM + mwarp + mi * 16 + (lane >> 2);
            int c = bx * BN + nwarp + ni * 8 + (lane & 3) * 2;
            *(float2*)&C[(size_t)r * N + c] =
                make_float2(acc[mi][ni][0], acc[mi][ni][1]);
            *(float2*)&C[(size_t)(r + 8) * N + c] =
                make_float2(acc[mi][ni][2], acc[mi][ni][3]);
        }
    }
#undef ISSUE
}

// ---------------------------------------------------------------------------
// RoPE in-place, fp32 math
// ---------------------------------------------------------------------------
__global__ void rope_kernel(const int* __restrict__ pos, float* __restrict__ qkv) {
    const int total = TT * (NHEAD + NKVH) * 64;
    int idx = blockIdx.x * blockDim.x + threadIdx.x;
    if (idx >= total) return;
    int i = idx & 63;
    int h = (idx >> 6) % (NHEAD + NKVH);
    int t = idx / ((NHEAD + NKVH) * 64);
    int col = (h < NHEAD) ? h * HD : QSIZE + (h - NHEAD) * HD;
    float* p = qkv + (size_t)t * QKVW + col + i;
    float inv = exp2f(-(float)i * 0.2958057710522857f);
    float fr = (float)pos[t] * inv;
    float s, c;
    sincosf(fr, &s, &c);
    float x1 = p[0], x2 = p[64];
    p[0]  = x1 * c - x2 * s;
    p[64] = x2 * c + x1 * s;
}

// ---------------------------------------------------------------------------
// FP16 tensor-core flash attention (m16n8k16), causal, GQA group=4.
// CTA = (head, 128-query block), 8 warps x 16 q-rows, KV tile 64.
// Q/K/V/P half in smem; V B-fragments via ldmatrix.x4.trans on [s][d].
// Softmax fp32 in registers, base-2.
// ---------------------------------------------------------------------------
#define ABQ  128
#define ABKV 64
#define QSH  136    // half stride (Q,K,V rows)
#define PSH  72     // half stride (P rows)
#define ATT_SMEM ((ABQ * QSH + ABKV * QSH + ABKV * QSH + ABQ * PSH) * 2)

__global__ __launch_bounds__(256, 2) void attn_h(const float* __restrict__ qkv,
                                                 __half* __restrict__ out) {
    extern __shared__ __half ash[];
    __half* Qs = ash;                      // [128][QSH]
    __half* Ks = Qs + ABQ * QSH;           // [64][QSH]
    __half* Vs = Ks + ABKV * QSH;          // [64][QSH]
    __half* Ps = Vs + ABKV * QSH;          // [128][PSH]

    const int h  = blockIdx.x;
    const int qb = gridDim.y - 1 - blockIdx.y;   // heavy tiles first
    const int kvh = h >> 2;
    const int tid = threadIdx.x;
    const int lane = tid & 31;
    const int wid = tid >> 5;
    const int q0 = wid * 16;
    const float qsc = 0.08838834764831845f * 1.4426950408889634f;

    // ---- load Q tile (scaled, half) ----
    {
        const float* qp = qkv + (size_t)(qb * ABQ) * QKVW + h * HD;
        for (int i = tid; i < ABQ * 32; i += 256) {
            int r = i >> 5, c = (i & 31) * 4;
            float4 v = *(const float4*)(qp + (size_t)r * QKVW + c);
            __half2 h0 = __floats2half2_rn(v.x * qsc, v.y * qsc);
            __half2 h1 = __floats2half2_rn(v.z * qsc, v.w * qsc);
            *(uint2*)(Qs + r * QSH + c) =
                make_uint2(*(uint32_t*)&h0, *(uint32_t*)&h1);
        }
    }

    float m0 = -1e30f, m1 = -1e30f, l0 = 0.f, l1 = 0.f;
    float o[16][4];
#pragma unroll
    for (int ni = 0; ni < 16; ni++)
#pragma unroll
        for (int r = 0; r < 4; r++) o[ni][r] = 0.f;

    const uint32_t qA =
        smem_u32(&Qs[(q0 + (lane & 15)) * QSH + (lane >> 4) * 8]);
    const uint32_t kB =
        smem_u32(&Ks[(((lane >> 4) << 3) + (lane & 7)) * QSH + ((lane >> 3) & 1) * 8]);
    const uint32_t pA =
        smem_u32(&Ps[(q0 + (lane & 15)) * PSH + (lane >> 4) * 8]);
    const uint32_t vB =
        smem_u32(&Vs[(lane & 15) * QSH + ((lane >> 4) << 3)]);

    const int rowg0 = qb * ABQ + q0;
    const int jmax = qb * 2 + 1;

    for (int j = 0; j <= jmax; j++) {
        __syncthreads();
        {
            const float* kp = qkv + (size_t)(j * ABKV) * QKVW + QSIZE + kvh * HD;
            const float* vp = kp + KVSIZE;
            for (int i = tid; i < ABKV * 32; i += 256) {
                int r = i >> 5, c = (i & 31) * 4;
                float4 kk = *(const float4*)(kp + (size_t)r * QKVW + c);
                __half2 k0 = __floats2half2_rn(kk.x, kk.y);
                __half2 k1 = __floats2half2_rn(kk.z, kk.w);
                *(uint2*)(Ks + r * QSH + c) =
                    make_uint2(*(uint32_t*)&k0, *(uint32_t*)&k1);
                float4 vv = *(const float4*)(vp + (size_t)r * QKVW + c);
                __half2 v0 = __floats2half2_rn(vv.x, vv.y);
                __half2 v1 = __floats2half2_rn(vv.z, vv.w);
                *(uint2*)(Vs + r * QSH + c) =
                    make_uint2(*(uint32_t*)&v0, *(uint32_t*)&v1);
            }
        }
        __syncthreads();

        if (j * ABKV <= rowg0 + 15) {
            // ---- S = Q @ K^T (8 k-steps of 16) ----
            float sA[8][4];
#pragma unroll
            for (int ni = 0; ni < 8; ni++)
#pragma unroll
                for (int r = 0; r < 4; r++) sA[ni][r] = 0.f;

#pragma unroll
            for (int kc = 0; kc < 8; kc++) {
                uint32_t a[4];
                ldsm4(a[0], a[1], a[2], a[3], qA + kc * 32);
#pragma unroll
                for (int ng = 0; ng < 4; ng++) {
                    uint32_t b[4];
                    ldsm4(b[0], b[1], b[2], b[3],
                          kB + ng * (16 * QSH * 2) + kc * 32);
                    mma_f16(sA[ng * 2],     a[0], a[1], a[2], a[3], b[0], b[1]);
                    mma_f16(sA[ng * 2 + 1], a[0], a[1], a[2], a[3], b[2], b[3]);
                }
            }

            // ---- causal mask ----
            if (j * ABKV + ABKV - 1 > rowg0) {
                int rg = rowg0 + (lane >> 2);
#pragma unroll
                for (int ni = 0; ni < 8; ni++) {
                    int c0 = j * ABKV + ni * 8 + (lane & 3) * 2;
                    if (c0     > rg)     sA[ni][0] = -INFINITY;
                    if (c0 + 1 > rg)     sA[ni][1] = -INFINITY;
                    if (c0     > rg + 8) sA[ni][2] = -INFINITY;
                    if (c0 + 1 > rg + 8) sA[ni][3] = -INFINITY;
                }
            }

            // ---- online softmax (base 2, fp32) ----
            float mx0 = -INFINITY, mx1 = -INFINITY;
#pragma unroll
            for (int ni = 0; ni < 8; ni++) {
                mx0 = fmaxf(mx0, fmaxf(sA[ni][0], sA[ni][1]));
                mx1 = fmaxf(mx1, fmaxf(sA[ni][2], sA[ni][3]));
            }
            mx0 = fmaxf(mx0, __shfl_xor_sync(0xffffffffu, mx0, 1));
            mx0 = fmaxf(mx0, __shfl_xor_sync(0xffffffffu, mx0, 2));
            mx1 = fmaxf(mx1, __shfl_xor_sync(0xffffffffu, mx1, 1));
            mx1 = fmaxf(mx1, __shfl_xor_sync(0xffffffffu, mx1, 2));

            float mn0 = fmaxf(m0, mx0), mn1 = fmaxf(m1, mx1);
            float cr0 = exp2f(m0 - mn0), cr1 = exp2f(m1 - mn1);
            m0 = mn0; m1 = mn1;

            float s0 = 0.f, s1 = 0.f;
            {
                int rq = q0 + (lane >> 2);
                __half* pr0 = &Ps[rq * PSH + (lane & 3) * 2];
                __half* pr1 = &Ps[(rq + 8) * PSH + (lane & 3) * 2];
#pragma unroll
                for (int ni = 0; ni < 8; ni++) {
                    float p0 = exp2f(sA[ni][0] - mn0);
                    float p1 = exp2f(sA[ni][1] - mn0);
                    float p2 = exp2f(sA[ni][2] - mn1);
                    float p3 = exp2f(sA[ni][3] - mn1);
                    s0 += p0 + p1;
                    s1 += p2 + p3;
                    *(__half2*)(pr0 + ni * 8) = __floats2half2_rn(p0, p1);
                    *(__half2*)(pr1 + ni * 8) = __floats2half2_rn(p2, p3);
                }
            }
            s0 += __shfl_xor_sync(0xffffffffu, s0, 1);
            s0 += __shfl_xor_sync(0xffffffffu, s0, 2);
            s1 += __shfl_xor_sync(0xffffffffu, s1, 1);
            s1 += __shfl_xor_sync(0xffffffffu, s1, 2);
            l0 = l0 * cr0 + s0;
            l1 = l1 * cr1 + s1;
#pragma unroll
            for (int ni = 0; ni < 16; ni++) {
                o[ni][0] *= cr0; o[ni][1] *= cr0;
                o[ni][2] *= cr1; o[ni][3] *= cr1;
            }
            __syncwarp();

            // ---- O += P @ V (4 s-steps of 16; V via ldmatrix.trans) ----
#pragma unroll
            for (int sk = 0; sk < 4; sk++) {
                uint32_t a[4];
                ldsm4(a[0], a[1], a[2], a[3], pA + sk * 32);
#pragma unroll
                for (int nb = 0; nb < 8; nb++) {
                    uint32_t v[4];
                    ldsm4t(v[0], v[1], v[2], v[3],
                           vB + sk * (16 * QSH * 2) + nb * 32);
                    mma_f16(o[nb * 2],     a[0], a[1], a[2], a[3], v[0], v[1]);
                    mma_f16(o[nb * 2 + 1], a[0], a[1], a[2], a[3], v[2], v[3]);
                }
            }
            __syncwarp();
        }
    }

    // ---- normalize, write half (feeds fp16 GEMM2 A-side) ----
    float i0 = 1.f / l0, i1 = 1.f / l1;
    int rg = qb * ABQ + q0 + (lane >> 2);
    __half* op = out + (size_t)rg * QSIZE + h * HD + (lane & 3) * 2;
#pragma unroll
    for (int ni = 0; ni < 16; ni++) {
        *(__half2*)(op + ni * 8) = __floats2half2_rn(o[ni][0] * i0, o[ni][1] * i0);
        *(__half2*)(op + (size_t)8 * QSIZE + ni * 8) =
            __floats2half2_rn(o[ni][2] * i1, o[ni][3] * i1);
    }
}

// ---------------------------------------------------------------------------
extern "C" void kernel_launch(void* const* d_in, const int* in_sizes, int n_in,
                              void* d_out, int out_size) {
    const int*   positions = (const int*)d_in[0];
    const float* hidden    = (const float*)d_in[1];
    const float* w_qkv     = (const float*)d_in[2];
    const float* w_o       = (const float*)d_in[3];
    float*       out       = (float*)d_out;

    void *qkv_p, *attn_p, *hid_p, *wqkvT_p, *woT_p;
    cudaGetSymbolAddress(&qkv_p, g_qkv);
    cudaGetSymbolAddress(&attn_p, g_attn16);
    cudaGetSymbolAddress(&hid_p, g_hid16);
    cudaGetSymbolAddress(&wqkvT_p, g_wqkvT);
    cudaGetSymbolAddress(&woT_p, g_woT);
    float*  qkv    = (float*)qkv_p;
    __half* attn16 = (__half*)attn_p;
    __half* hid16  = (__half*)hid_p;
    __half* wqkvT  = (__half*)wqkvT_p;
    __half* woT    = (__half*)woT_p;

    cudaFuncSetAttribute(attn_h, cudaFuncAttributeMaxDynamicSharedMemorySize,
                         ATT_SMEM);
    cudaFuncSetAttribute(hgemm, cudaFuncAttributeMaxDynamicSharedMemorySize,
                         TG_SMEM);

    // 0) pre-passes: hidden -> half; weights -> transposed half [N][K]
    {
        int n4 = TT * HH / 4;
        conv_half<<<(n4 + 255) / 256, 256>>>(hidden, hid16, n4);
        dim3 tb(32, 8);
        transpose_half<<<dim3(QKVW / 32, HH / 32), tb>>>(w_qkv, wqkvT, HH, QKVW);
        transpose_half<<<dim3(HH / 32, QSIZE / 32), tb>>>(w_o, woT, QSIZE, HH);
    }
    // 1) qkv = hid @ w_qkv  (fp16 TC)
    {
        dim3 grid(QKVW / BN, TT / BM);
        hgemm<<<grid, 256, TG_SMEM>>>(hid16, wqkvT, qkv, TT, QKVW, HH);
    }
    // 2) RoPE (fp32)
    {
        int total = TT * (NHEAD + NKVH) * 64;
        rope_kernel<<<(total + 255) / 256, 256>>>(positions, qkv);
    }
    // 3) attention (fp16 TC flash), half output
    {
        dim3 grid(NHEAD, TT / ABQ);
        attn_h<<<grid, 256, ATT_SMEM>>>(qkv, attn16);
    }
    // 4) out = attn @ w_o  (fp16 TC)
    {
        dim3 grid(HH / BN, TT / BM);
        hgemm<<<grid, 256, TG_SMEM>>>(attn16, woT, out, TT, HH, QSIZE);
    }
}